// round 7
// baseline (speedup 1.0000x reference)
#include <cuda_runtime.h>
#include <cuda_fp16.h>
#include <cstdint>
#include <math.h>

// ---------------- scratch (static device globals; no allocation) ----------------
__device__ float g_q[16 * 4096];
__device__ __half g_sh[16 * 4096];      // softmax scores, fp16 packed
__device__ float g_y[16 * 256];
__device__ float g_ctx[16 * 256];
// x as fp16, SAME layout as x: [b][c][n]
__device__ __half g_xh[(size_t)16 * 256 * 4096];
// W_v rows (257..512) fp16, row-major [256 m][256 k]
__device__ __half g_wh[256 * 256];

__device__ __forceinline__ uint32_t smem_u32(const void* p) {
    uint32_t a;
    asm("{ .reg .u64 t; cvta.to.shared.u64 t, %1; cvt.u32.u64 %0, t; }" : "=r"(a) : "l"(p));
    return a;
}

#define LDSM_X4(r, addr) \
    asm volatile("ldmatrix.sync.aligned.m8n8.x4.shared.b16 {%0,%1,%2,%3}, [%4];" \
        : "=r"((r)[0]), "=r"((r)[1]), "=r"((r)[2]), "=r"((r)[3]) : "r"(addr))
#define LDSM_X4T(r, addr) \
    asm volatile("ldmatrix.sync.aligned.m8n8.x4.trans.shared.b16 {%0,%1,%2,%3}, [%4];" \
        : "=r"((r)[0]), "=r"((r)[1]), "=r"((r)[2]), "=r"((r)[3]) : "r"(addr))
#define MMA_F16(d, a, b0, b1) \
    asm volatile("mma.sync.aligned.m16n8k16.row.col.f32.f16.f16.f32 " \
        "{%0,%1,%2,%3}, {%4,%5,%6,%7}, {%8,%9}, {%0,%1,%2,%3};" \
        : "+f"((d)[0]), "+f"((d)[1]), "+f"((d)[2]), "+f"((d)[3]) \
        : "r"((a)[0]), "r"((a)[1]), "r"((a)[2]), "r"((a)[3]), "r"(b0), "r"(b1))
#define CP_ASYNC16(dst, src) \
    asm volatile("cp.async.cg.shared.global [%0], [%1], 16;" :: "r"(dst), "l"(src))
#define CP_COMMIT() asm volatile("cp.async.commit_group;" ::: "memory")
#define CP_WAIT(n)  asm volatile("cp.async.wait_group %0;" :: "n"(n) : "memory")

// ---------------------------------------------------------------------------
// Kernel A: W_v (rows 257..512) -> fp16.
// ---------------------------------------------------------------------------
__global__ __launch_bounds__(256) void conv_w(const float* __restrict__ W)
{
    int r = blockIdx.x, c = threadIdx.x;
    g_wh[r * 256 + c] = __float2half_rn(W[(size_t)(257 + r) * 256 + c]);
}

// ---------------------------------------------------------------------------
// Kernel B: x -> fp16 (same layout) and q[b,n] = sum_c W[0,c]*x[b,c,n].
// Grid (16 n-tiles of 256, 16 b), 256 threads.
// ---------------------------------------------------------------------------
__global__ __launch_bounds__(256) void conv_xq(const float* __restrict__ x,
                                               const float* __restrict__ W)
{
    __shared__ float s_wq[256];
    __shared__ float s_red[4][256];
    const int b = blockIdx.y;
    const int nBase = blockIdx.x * 256;
    const int t = threadIdx.x;
    const int cq = t >> 6;
    const int n = (t & 63) * 4;

    s_wq[t] = W[t];  // W row 0 = q weights
    __syncthreads();

    float qp0 = 0.f, qp1 = 0.f, qp2 = 0.f, qp3 = 0.f;
#pragma unroll 8
    for (int c = cq; c < 256; c += 4) {
        size_t idx = ((size_t)b * 256 + c) * 4096 + nBase + n;
        float4 v = *(const float4*)(x + idx);
        __half2 h01 = __floats2half2_rn(v.x, v.y);
        __half2 h23 = __floats2half2_rn(v.z, v.w);
        uint2 pk;
        pk.x = *(uint32_t*)&h01;
        pk.y = *(uint32_t*)&h23;
        *(uint2*)(g_xh + idx) = pk;
        float wq = s_wq[c];
        qp0 += wq * v.x; qp1 += wq * v.y; qp2 += wq * v.z; qp3 += wq * v.w;
    }
    *(float4*)&s_red[cq][n] = make_float4(qp0, qp1, qp2, qp3);
    __syncthreads();
    g_q[b * 4096 + nBase + t] =
        s_red[0][t] + s_red[1][t] + s_red[2][t] + s_red[3][t];
}

// ---------------------------------------------------------------------------
// Kernel C: softmax over q (16 x 4096); emits scores as packed fp16.
// ---------------------------------------------------------------------------
__global__ __launch_bounds__(512) void softmax_k()
{
    const int b = blockIdx.x;
    const float4* q4 = (const float4*)(g_q + b * 4096);

    float4 v0 = q4[threadIdx.x];
    float4 v1 = q4[threadIdx.x + 512];

    float m = fmaxf(fmaxf(fmaxf(v0.x, v0.y), fmaxf(v0.z, v0.w)),
                    fmaxf(fmaxf(v1.x, v1.y), fmaxf(v1.z, v1.w)));
    __shared__ float redm[16];
    __shared__ float reds[16];
#pragma unroll
    for (int o = 16; o > 0; o >>= 1) m = fmaxf(m, __shfl_xor_sync(0xffffffffu, m, o));
    if ((threadIdx.x & 31) == 0) redm[threadIdx.x >> 5] = m;
    __syncthreads();
    float gm = redm[0];
#pragma unroll
    for (int i = 1; i < 16; i++) gm = fmaxf(gm, redm[i]);

    v0.x = __expf(v0.x - gm); v0.y = __expf(v0.y - gm);
    v0.z = __expf(v0.z - gm); v0.w = __expf(v0.w - gm);
    v1.x = __expf(v1.x - gm); v1.y = __expf(v1.y - gm);
    v1.z = __expf(v1.z - gm); v1.w = __expf(v1.w - gm);

    float sum = v0.x + v0.y + v0.z + v0.w + v1.x + v1.y + v1.z + v1.w;
#pragma unroll
    for (int o = 16; o > 0; o >>= 1) sum += __shfl_xor_sync(0xffffffffu, sum, o);
    if ((threadIdx.x & 31) == 0) reds[threadIdx.x >> 5] = sum;
    __syncthreads();
    float tot = 0.f;
#pragma unroll
    for (int i = 0; i < 16; i++) tot += reds[i];
    float inv = 1.f / tot;

    v0.x *= inv; v0.y *= inv; v0.z *= inv; v0.w *= inv;
    v1.x *= inv; v1.y *= inv; v1.z *= inv; v1.w *= inv;

    __half2 a0 = __floats2half2_rn(v0.x, v0.y);
    __half2 a1 = __floats2half2_rn(v0.z, v0.w);
    __half2 b0 = __floats2half2_rn(v1.x, v1.y);
    __half2 b1 = __floats2half2_rn(v1.z, v1.w);
    uint2 p0, p1;
    p0.x = *(uint32_t*)&a0; p0.y = *(uint32_t*)&a1;
    p1.x = *(uint32_t*)&b0; p1.y = *(uint32_t*)&b1;
    *(uint2*)(g_sh + b * 4096 + threadIdx.x * 4)         = p0;
    *(uint2*)(g_sh + b * 4096 + (threadIdx.x + 512) * 4) = p1;
}

// ---------------------------------------------------------------------------
// Kernel D: y[b,c] = sum_n x[b,c,n] * s[b,n]  (both fp16, fp32 accumulate).
// Grid (64 c-tiles of 4, 16 b), 256 thr: 2 warps per c-row (n halves),
// 8 independent uint4 x + uint4 s loads per lane (s hits L2: 8KB per b).
// ---------------------------------------------------------------------------
__global__ __launch_bounds__(256) void y_kernel()
{
    const int b = blockIdx.y;
    const int t = threadIdx.x;
    const int w = t >> 5, L = t & 31;
    const int c = blockIdx.x * 4 + (w >> 1);
    const int half = w & 1;

    const uint4* xr = (const uint4*)(g_xh + ((size_t)b * 256 + c) * 4096);
    const uint4* sr = (const uint4*)(g_sh + b * 4096);
    float acc = 0.f;
#pragma unroll
    for (int k = 0; k < 8; k++) {
        int i = half * 256 + k * 32 + L;
        uint4 xv = xr[i];
        uint4 sv = sr[i];
        float2 x0 = __half22float2(*(__half2*)&xv.x);
        float2 s0 = __half22float2(*(__half2*)&sv.x);
        float2 x1 = __half22float2(*(__half2*)&xv.y);
        float2 s1 = __half22float2(*(__half2*)&sv.y);
        float2 x2 = __half22float2(*(__half2*)&xv.z);
        float2 s2 = __half22float2(*(__half2*)&sv.z);
        float2 x3 = __half22float2(*(__half2*)&xv.w);
        float2 s3 = __half22float2(*(__half2*)&sv.w);
        acc += x0.x * s0.x + x0.y * s0.y + x1.x * s1.x + x1.y * s1.y;
        acc += x2.x * s2.x + x2.y * s2.y + x3.x * s3.x + x3.y * s3.y;
    }
#pragma unroll
    for (int o = 16; o > 0; o >>= 1) acc += __shfl_xor_sync(0xffffffffu, acc, o);
    __shared__ float red[8];
    if (L == 0) red[w] = acc;
    __syncthreads();
    if (t < 4) g_y[b * 256 + blockIdx.x * 4 + t] = red[t * 2] + red[t * 2 + 1];
}

// ---------------------------------------------------------------------------
// Kernel E: ctx[b,d] = sum_c W[1+d,c] * y[b,c]. One warp per d, coalesced.
// ---------------------------------------------------------------------------
__global__ __launch_bounds__(256) void ctx_kernel(const float* __restrict__ W)
{
    const int b = blockIdx.x;
    const int w = threadIdx.x >> 5, l = threadIdx.x & 31;
    const int d = blockIdx.y * 8 + w;
    __shared__ float ys[256];
    ys[threadIdx.x] = g_y[b * 256 + threadIdx.x];
    __syncthreads();
    const float* wr = W + (size_t)(1 + d) * 256;
    float acc = 0.f;
#pragma unroll
    for (int c = l; c < 256; c += 32) acc += wr[c] * ys[c];
#pragma unroll
    for (int o = 16; o > 0; o >>= 1) acc += __shfl_xor_sync(0xffffffffu, acc, o);
    if (l == 0) g_ctx[b * 256 + d] = acc;
}

// ---------------------------------------------------------------------------
// Kernel F: mma.sync fp16 GEMM  V = Wv @ x  (M=256 x N=65536 x K=256).
// CTA tile 128(m) x 128(n), 256 thr, 2-stage cp.async ring (2 x 32KB smem)
// -> 2 CTAs/SM: cross-CTA overlap hides stage-boundary syncs.
// 8 warps, warp tile 64x32 (2 m-warps x 4 n-warps). Epilogue: relu(V)*ctx.
// Stage: A@0 (128r x 128B, sw128 xor), B@16K (64r x 256B, xor row&15)
// ---------------------------------------------------------------------------
#define STAGE_BYTES 32768

__global__ __launch_bounds__(256, 2) void gemm_tc(float* __restrict__ out)
{
    extern __shared__ char sm[];
    __shared__ float s_ctx[128];

    const int nBase = blockIdx.x * 128;
    const int mBase = blockIdx.y * 128;
    const int b = blockIdx.z;
    const uint32_t smb = smem_u32(sm);

    const int t = threadIdx.x;
    const int w = t >> 5, L = t & 31;
    const int mw = w & 1, nw = w >> 1;

    if (t < 128) s_ctx[t] = g_ctx[b * 256 + mBase + t];

    const int ra = t >> 1, ca = t & 1;  // A: 128 rows x 2 col-groups of 4x16B
    const int rb = t >> 2, cb = t & 3;  // B: 64 rows x 4 col-groups of 4x16B

    auto stage = [&](int ch, int buf) {
        const int k0 = ch * 64;
        const uint32_t base = smb + buf * STAGE_BYTES;
#pragma unroll
        for (int i = 0; i < 4; i++) {
            int c16 = ca * 4 + i;
            uint32_t offA = (uint32_t)(ra * 128 + c16 * 16);
            uint32_t swA = offA ^ ((offA >> 3) & 0x70);
            CP_ASYNC16(base + swA, g_wh + (size_t)(mBase + ra) * 256 + k0 + c16 * 8);
            int c16b = cb * 4 + i;
            uint32_t offB = (uint32_t)(rb * 256 + c16b * 16);
            uint32_t swB = offB ^ (((offB >> 8) & 0xF) << 4);
            CP_ASYNC16(base + 16384 + swB,
                       g_xh + ((size_t)b * 256 + k0 + rb) * 4096 + nBase + c16b * 8);
        }
        CP_COMMIT();
    };

    float acc[4][4][4];
#pragma unroll
    for (int i = 0; i < 4; i++)
#pragma unroll
        for (int j = 0; j < 4; j++)
#pragma unroll
            for (int k = 0; k < 4; k++) acc[i][j][k] = 0.f;

    const int rowL = L & 15;
    const int selL = L >> 4;

    stage(0, 0);
    stage(1, 1);

#pragma unroll
    for (int ch = 0; ch < 4; ch++) {
        CP_WAIT(1);
        __syncthreads();
        const uint32_t base = smb + (ch & 1) * STAGE_BYTES;
#pragma unroll
        for (int ks = 0; ks < 4; ks++) {
            uint32_t Ah[4][4], B[2][4];
#pragma unroll
            for (int mf = 0; mf < 4; mf++) {
                uint32_t offA = (uint32_t)((mw * 64 + mf * 16 + rowL) * 128 +
                                           (ks * 2 + selL) * 16);
                LDSM_X4(Ah[mf], base + (offA ^ ((offA >> 3) & 0x70)));
            }
#pragma unroll
            for (int ng = 0; ng < 2; ng++) {
                uint32_t offB = (uint32_t)((ks * 16 + rowL) * 256 +
                                           (nw * 4 + ng * 2 + selL) * 16);
                LDSM_X4T(B[ng], base + 16384 + (offB ^ (((offB >> 8) & 0xF) << 4)));
            }
#pragma unroll
            for (int mf = 0; mf < 4; mf++)
#pragma unroll
                for (int nf = 0; nf < 4; nf++) {
                    const int ng = nf >> 1, p = (nf & 1) * 2;
                    MMA_F16(acc[mf][nf], Ah[mf], B[ng][p], B[ng][p + 1]);
                }
        }
        if (ch < 2) {
            __syncthreads();       // stage buffer consumed by all warps
            stage(ch + 2, ch & 1);
        }
    }

    // ---- epilogue: out = relu(V) * ctx ----
    const int gid = L >> 2, tig = L & 3;
#pragma unroll
    for (int mf = 0; mf < 4; mf++) {
        const int r0 = mw * 64 + mf * 16 + gid;
        const float c0 = s_ctx[r0], c1 = s_ctx[r0 + 8];
        float* o0 = out + ((size_t)b * 256 + mBase + r0) * 4096 + nBase;
        float* o1 = o0 + (size_t)8 * 4096;
#pragma unroll
        for (int nf = 0; nf < 4; nf++) {
            const int col = nw * 32 + nf * 8 + tig * 2;
            float2 v0 = make_float2(fmaxf(acc[mf][nf][0], 0.f) * c0,
                                    fmaxf(acc[mf][nf][1], 0.f) * c0);
            float2 v1 = make_float2(fmaxf(acc[mf][nf][2], 0.f) * c1,
                                    fmaxf(acc[mf][nf][3], 0.f) * c1);
            *(float2*)(o0 + col) = v0;
            *(float2*)(o1 + col) = v1;
        }
    }
}

// ---------------------------------------------------------------------------
extern "C" void kernel_launch(void* const* d_in, const int* in_sizes, int n_in,
                              void* d_out, int out_size)
{
    const float* x = (const float*)d_in[0];  // (16, 256, 64, 64) f32
    const float* W = (const float*)d_in[1];  // (513, 256) f32
    float* out = (float*)d_out;              // (16, 256, 64, 64) f32

    cudaFuncSetAttribute(gemm_tc, cudaFuncAttributeMaxDynamicSharedMemorySize,
                         2 * STAGE_BYTES);

    conv_w<<<256, 256>>>(W);
    conv_xq<<<dim3(16, 16), 256>>>(x, W);
    softmax_k<<<16, 512>>>();
    y_kernel<<<dim3(64, 16), 256>>>();
    ctx_kernel<<<dim3(16, 32), 256>>>(W);
    gemm_tc<<<dim3(32, 2, 16), 256, 2 * STAGE_BYTES>>>(out);
}